// round 6
// baseline (speedup 1.0000x reference)
#include <cuda_runtime.h>
#include <cstdint>
#include <cstring>

#define R_TOTAL 4403
#define BATCH   32
#define D_MODEL 4096
#define RT      64          // rows per CTA
#define KT      32          // k per smem tile
#define SPLITK  8
#define KC      (D_MODEL / SPLITK)   // 512 k per CTA
#define NOUT    (BATCH * R_TOTAL)

typedef unsigned long long ull;

// Scratch (allocation-free rule: __device__ globals)
__device__ __align__(16) float g_xxd[D_MODEL * 64];       // x transposed+duplicated+permuted: [k][64]
__device__ float g_part[SPLITK * NOUT];                   // split-K partials

// Packed fp32x2 FMA (Blackwell sm_100+): d = a*b + d elementwise on 2 packed floats
#define FMA2(acc, a, b) asm("fma.rn.f32x2 %0, %1, %2, %0;" : "+l"(acc) : "l"(a), "l"(b))

// ---------------------------------------------------------------------------
// Prep: g_xxd[k][col(b)..col(b)+1] = (x[b][k], x[b][k])  (duplicated pair)
// Permutation puts each thread-group's 4 b-pairs at conflict-free offsets:
//   A-half [0,32) floats: pairs b=4t, 4t+1 at floats t*4..t*4+3
//   B-half [32,64):       pairs b=4t+2, 4t+3
// col(b) = ((b&2)<<4) | ((b>>2)<<2) | ((b&1)<<1)
// ---------------------------------------------------------------------------
__global__ void prep_kernel(const float* __restrict__ x) {
    int gid = blockIdx.x * blockDim.x + threadIdx.x;   // 131072 total
    int b = gid & 31;
    int k = gid >> 5;
    float v = x[b * D_MODEL + k];
    int col = ((b & 2) << 4) | ((b >> 2) << 2) | ((b & 1) << 1);
    float2 vv = make_float2(v, v);
    *reinterpret_cast<float2*>(&g_xxd[k * 64 + col]) = vv;
}

// ---------------------------------------------------------------------------
// Main GEMM: grid (ceil(R/64), SPLITK), 128 threads.
// Thread (tb = tid&7, tr = tid>>3) computes 4 batches x 4 rows as 8 f32x2 accs.
// ---------------------------------------------------------------------------
__global__ __launch_bounds__(128) void gemm_kernel(const float* __restrict__ w,
                                                   const int* __restrict__ idx) {
    __shared__ __align__(16) float w_s[KT * 64];    // [k][r] transposed
    __shared__ __align__(16) float xx_s[KT * 64];   // [k][permuted dup b]
    __shared__ int idx_s[RT];

    int tid   = threadIdx.x;
    int rbase = blockIdx.x * RT;
    int kc    = blockIdx.y;

    if (tid < RT) {
        int r = rbase + tid;
        idx_s[tid] = (r < R_TOTAL) ? idx[r] : 0;
    }
    __syncthreads();

    int tb = tid & 7;       // batch group (4 batches)
    int tr = tid >> 3;      // row group (4 rows), 0..15
    int wr = tid >> 1;      // w-load: row (2 threads per row)
    int wh = tid & 1;       // w-load: which 64B half of the 128B chunk

    const float* wrow = w + (size_t)idx_s[wr] * D_MODEL + wh * 16;

    ull acc[8];
#pragma unroll
    for (int a = 0; a < 8; a++) acc[a] = 0ull;

    for (int t = 0; t < KC / KT; ++t) {
        int k0 = kc * KC + t * KT;
        __syncthreads();   // protect smem from previous tile's readers

        // --- load W tile (64 rows x 32 floats), transpose into w_s[k][r] ---
        // LDG: 2 lanes cover one row's 128B line -> minimal wavefronts.
        // STS: 2-way conflict only (16 rows x 2 halves per inst).
#pragma unroll
        for (int c = 0; c < 4; ++c) {
            float4 v = *reinterpret_cast<const float4*>(wrow + k0 + c * 4);
            int kk = wh * 16 + c * 4;
            w_s[(kk + 0) * 64 + wr] = v.x;
            w_s[(kk + 1) * 64 + wr] = v.y;
            w_s[(kk + 2) * 64 + wr] = v.z;
            w_s[(kk + 3) * 64 + wr] = v.w;
        }

        // --- load XX tile (straight copy, already transposed/dup/permuted) ---
#pragma unroll
        for (int t2 = 0; t2 < 4; ++t2) {
            int i   = tid + t2 * 128;
            int row = i >> 4;
            int c16 = i & 15;
            float4 v = *reinterpret_cast<const float4*>(&g_xxd[(size_t)(k0 + row) * 64 + c16 * 4]);
            *reinterpret_cast<float4*>(&xx_s[row * 64 + c16 * 4]) = v;
        }
        __syncthreads();

        // --- compute: per k, 3 conflict-free LDS.128 + 8 FFMA2 ---
#pragma unroll
        for (int k = 0; k < KT; ++k) {
            ulonglong2 xa = *reinterpret_cast<const ulonglong2*>(&xx_s[k * 64 + tb * 4]);       // dup(b0), dup(b1)
            ulonglong2 xb = *reinterpret_cast<const ulonglong2*>(&xx_s[k * 64 + 32 + tb * 4]);  // dup(b2), dup(b3)
            ulonglong2 wv = *reinterpret_cast<const ulonglong2*>(&w_s[k * 64 + tr * 4]);        // (r0,r1), (r2,r3)
            FMA2(acc[0], xa.x, wv.x);
            FMA2(acc[1], xa.x, wv.y);
            FMA2(acc[2], xa.y, wv.x);
            FMA2(acc[3], xa.y, wv.y);
            FMA2(acc[4], xb.x, wv.x);
            FMA2(acc[5], xb.x, wv.y);
            FMA2(acc[6], xb.y, wv.x);
            FMA2(acc[7], xb.y, wv.y);
        }
    }

    // --- epilogue: write partials (deterministic, no atomics) ---
    float* base = g_part + (size_t)kc * NOUT;
#pragma unroll
    for (int a = 0; a < 8; ++a) {
        int b = tb * 4 + (a >> 1);
        int r = rbase + tr * 4 + (a & 1) * 2;
        float2 f;
        memcpy(&f, &acc[a], 8);
        if (r < R_TOTAL)     base[b * R_TOTAL + r]     = f.x;
        if (r + 1 < R_TOTAL) base[b * R_TOTAL + r + 1] = f.y;
    }
}

// ---------------------------------------------------------------------------
// Reduce split-K partials -> final output (also un-poisons d_out fully)
// ---------------------------------------------------------------------------
__global__ void reduce_kernel(float* __restrict__ out) {
    int i = blockIdx.x * blockDim.x + threadIdx.x;
    if (i < NOUT) {
        float s = 0.f;
#pragma unroll
        for (int c = 0; c < SPLITK; ++c) s += g_part[(size_t)c * NOUT + i];
        out[i] = s;
    }
}

extern "C" void kernel_launch(void* const* d_in, const int* in_sizes, int n_in,
                              void* d_out, int out_size) {
    const float* x   = (const float*)d_in[0];   // (32, 1, 4096) f32
    const float* w   = (const float*)d_in[1];   // (11008, 4096) f32
    const int*   idx = (const int*)d_in[2];     // (4403,) i32
    float* out = (float*)d_out;                 // (32, 1, 4403) f32

    prep_kernel<<<(D_MODEL * BATCH) / 256, 256>>>(x);
    gemm_kernel<<<dim3((R_TOTAL + RT - 1) / RT, SPLITK), 128>>>(w, idx);
    reduce_kernel<<<(NOUT + 255) / 256, 256>>>(out);
}

// round 15
// speedup vs baseline: 1.7669x; 1.7669x over previous
#include <cuda_runtime.h>
#include <cuda_bf16.h>
#include <cstdint>

#define R_TOTAL 4403
#define BATCH   32
#define D_MODEL 4096
#define MT      128                    // gathered rows per CTA
#define SPLITK  8
#define KC      (D_MODEL / SPLITK)     // 512 k per CTA
#define CHUNK   64                     // k per smem stage
#define NCHUNK  (KC / CHUNK)           // 8
#define NOUT    (BATCH * R_TOTAL)
#define NTILE   ((R_TOTAL + MT - 1) / MT)   // 35
#define SPB     144                    // smem row pitch bytes (72 bf16): 144/4=36 banks -> +4/row, conflict-free frags

// split-K partials (allocation-free rule: __device__ global)
__device__ float g_part[SPLITK * NOUT];

__device__ __forceinline__ uint32_t pk(float lo, float hi) {   // pack {lo,hi} -> bf16x2 (lo in low half)
    uint32_t r;
    asm("cvt.rn.bf16x2.f32 %0, %1, %2;" : "=r"(r) : "f"(hi), "f"(lo));
    return r;
}

// m16n8k16 row.col f32.bf16.bf16.f32 (sm_80+, assembles for plain sm_103)
#define MMA(c, a, b0, b1) \
    asm volatile("mma.sync.aligned.m16n8k16.row.col.f32.bf16.bf16.f32 " \
        "{%0,%1,%2,%3}, {%4,%5,%6,%7}, {%8,%9}, {%0,%1,%2,%3};" \
        : "+f"((c)[0]), "+f"((c)[1]), "+f"((c)[2]), "+f"((c)[3]) \
        : "r"((a)[0]), "r"((a)[1]), "r"((a)[2]), "r"((a)[3]), "r"(b0), "r"(b1))

// ---------------------------------------------------------------------------
// GEMM: grid (35, 8), 256 threads (8 warps). Warp w owns rows [w*16, w*16+16).
// D[m,n] = sum_k W[idx[m],k]*x[n,k] via bf16 hi/lo 3-product split, f32 accum.
// ---------------------------------------------------------------------------
__global__ __launch_bounds__(256, 2) void gemm_tc(const float* __restrict__ w,
                                                  const float* __restrict__ x,
                                                  const int* __restrict__ idx) {
    __shared__ __align__(16) char whi_s[MT * SPB];      // 18432 B
    __shared__ __align__(16) char wlo_s[MT * SPB];      // 18432 B
    __shared__ __align__(16) char xhi_s[BATCH * SPB];   //  4608 B
    __shared__ __align__(16) char xlo_s[BATCH * SPB];   //  4608 B
    __shared__ int idx_s[MT];                           // total 46592 B < 48K

    int tid = threadIdx.x, wid = tid >> 5, lane = tid & 31;
    int g = lane >> 2, t4 = lane & 3;
    int rbase = blockIdx.x * MT;
    int kbase = blockIdx.y * KC;

    if (tid < MT) { int r = rbase + tid; idx_s[tid] = (r < R_TOTAL) ? idx[r] : 0; }
    __syncthreads();

    // W staging: 2 threads per row, 32 floats (128B line halves) each
    int row = tid >> 1, half = tid & 1;
    const float* wrow = w + (size_t)idx_s[row] * D_MODEL + kbase + half * 32;
    // X staging: 8 threads per batch row, 8 floats each
    int xrow = tid >> 3, xseg = tid & 7;
    const float* xsrc = x + (size_t)xrow * D_MODEL + kbase + xseg * 8;

    float acc[4][4];
#pragma unroll
    for (int i = 0; i < 4; ++i)
#pragma unroll
        for (int j = 0; j < 4; ++j) acc[i][j] = 0.f;

    // prefetch chunk 0 into registers
    float4 wreg[8], xr0, xr1;
#pragma unroll
    for (int j = 0; j < 8; ++j) wreg[j] = *(const float4*)(wrow + j * 4);
    xr0 = *(const float4*)(xsrc);
    xr1 = *(const float4*)(xsrc + 4);

    for (int c = 0; c < NCHUNK; ++c) {
        // ---- stage W hi/lo (bf16 split) into padded smem ----
#pragma unroll
        for (int jj = 0; jj < 4; ++jj) {
            float4 v0 = wreg[jj * 2], v1 = wreg[jj * 2 + 1];
            float f[8] = {v0.x, v0.y, v0.z, v0.w, v1.x, v1.y, v1.z, v1.w};
            uint32_t hw[4], lw[4];
#pragma unroll
            for (int e = 0; e < 4; ++e) {
                float a0 = f[e * 2], a1 = f[e * 2 + 1];
                float h0 = __bfloat162float(__float2bfloat16_rn(a0));
                float h1 = __bfloat162float(__float2bfloat16_rn(a1));
                hw[e] = pk(h0, h1);
                lw[e] = pk(a0 - h0, a1 - h1);
            }
            uint32_t off = (uint32_t)(row * SPB + half * 64 + jj * 16);
            *(uint4*)(whi_s + off) = make_uint4(hw[0], hw[1], hw[2], hw[3]);
            *(uint4*)(wlo_s + off) = make_uint4(lw[0], lw[1], lw[2], lw[3]);
        }
        // ---- stage X hi/lo ----
        {
            float f[8] = {xr0.x, xr0.y, xr0.z, xr0.w, xr1.x, xr1.y, xr1.z, xr1.w};
            uint32_t hw[4], lw[4];
#pragma unroll
            for (int e = 0; e < 4; ++e) {
                float a0 = f[e * 2], a1 = f[e * 2 + 1];
                float h0 = __bfloat162float(__float2bfloat16_rn(a0));
                float h1 = __bfloat162float(__float2bfloat16_rn(a1));
                hw[e] = pk(h0, h1);
                lw[e] = pk(a0 - h0, a1 - h1);
            }
            uint32_t off = (uint32_t)(xrow * SPB + xseg * 16);
            *(uint4*)(xhi_s + off) = make_uint4(hw[0], hw[1], hw[2], hw[3]);
            *(uint4*)(xlo_s + off) = make_uint4(lw[0], lw[1], lw[2], lw[3]);
        }
        __syncthreads();

        // prefetch next chunk (LDGs overlap the MMA/LDS compute below)
        if (c + 1 < NCHUNK) {
#pragma unroll
            for (int j = 0; j < 8; ++j)
                wreg[j] = *(const float4*)(wrow + (c + 1) * CHUNK + j * 4);
            xr0 = *(const float4*)(xsrc + (c + 1) * CHUNK);
            xr1 = *(const float4*)(xsrc + (c + 1) * CHUNK + 4);
        }

        // ---- compute: 4 k-steps x 4 n-tiles x 3 products ----
        int arow0 = (wid * 16 + g) * SPB;
#pragma unroll
        for (int ks = 0; ks < 4; ++ks) {
            int ko = ks * 32 + t4 * 4;    // byte offset of this lane's k-pair
            uint32_t ah[4], al[4];
            ah[0] = *(const uint32_t*)(whi_s + arow0 + ko);
            ah[1] = *(const uint32_t*)(whi_s + arow0 + 8 * SPB + ko);
            ah[2] = *(const uint32_t*)(whi_s + arow0 + ko + 16);
            ah[3] = *(const uint32_t*)(whi_s + arow0 + 8 * SPB + ko + 16);
            al[0] = *(const uint32_t*)(wlo_s + arow0 + ko);
            al[1] = *(const uint32_t*)(wlo_s + arow0 + 8 * SPB + ko);
            al[2] = *(const uint32_t*)(wlo_s + arow0 + ko + 16);
            al[3] = *(const uint32_t*)(wlo_s + arow0 + 8 * SPB + ko + 16);
#pragma unroll
            for (int nt = 0; nt < 4; ++nt) {
                int brow = (nt * 8 + g) * SPB;
                uint32_t bh0 = *(const uint32_t*)(xhi_s + brow + ko);
                uint32_t bh1 = *(const uint32_t*)(xhi_s + brow + ko + 16);
                uint32_t bl0 = *(const uint32_t*)(xlo_s + brow + ko);
                uint32_t bl1 = *(const uint32_t*)(xlo_s + brow + ko + 16);
                MMA(acc[nt], ah, bh0, bh1);   // Whi * Xhi
                MMA(acc[nt], ah, bl0, bl1);   // Whi * Xlo
                MMA(acc[nt], al, bh0, bh1);   // Wlo * Xhi
            }
        }
        __syncthreads();
    }

    // ---- epilogue: write split-K partials (deterministic) ----
    float* base = g_part + (size_t)blockIdx.y * NOUT;
    int r0 = rbase + wid * 16 + g;
    int r1 = r0 + 8;
#pragma unroll
    for (int nt = 0; nt < 4; ++nt) {
        int n = nt * 8 + t4 * 2;
        if (r0 < R_TOTAL) {
            base[(size_t)n * R_TOTAL + r0]       = acc[nt][0];
            base[(size_t)(n + 1) * R_TOTAL + r0] = acc[nt][1];
        }
        if (r1 < R_TOTAL) {
            base[(size_t)n * R_TOTAL + r1]       = acc[nt][2];
            base[(size_t)(n + 1) * R_TOTAL + r1] = acc[nt][3];
        }
    }
}

// ---------------------------------------------------------------------------
// Reduce split-K partials -> output (covers/unpoisons all NOUT elements)
// ---------------------------------------------------------------------------
__global__ void reduce_kernel(float* __restrict__ out) {
    int i = blockIdx.x * blockDim.x + threadIdx.x;
    if (i < NOUT) {
        float s = 0.f;
#pragma unroll
        for (int c = 0; c < SPLITK; ++c) s += g_part[(size_t)c * NOUT + i];
        out[i] = s;
    }
}

extern "C" void kernel_launch(void* const* d_in, const int* in_sizes, int n_in,
                              void* d_out, int out_size) {
    const float* x   = (const float*)d_in[0];   // (32, 1, 4096) f32
    const float* w   = (const float*)d_in[1];   // (11008, 4096) f32
    const int*   idx = (const int*)d_in[2];     // (4403,) i32
    float* out = (float*)d_out;                 // (32, 1, 4403) f32

    gemm_tc<<<dim3(NTILE, SPLITK), 256>>>(w, x, idx);
    reduce_kernel<<<(NOUT + 255) / 256, 256>>>(out);
}